// round 16
// baseline (speedup 1.0000x reference)
#include <cuda_runtime.h>
#include <cuda_bf16.h>

// Problem constants: B=32, M=32768, D=128, R=64, W=129
#define RB_B 32
#define RB_M 32768
#define RB_D 128
#define RB_W 129

// Strategy this round: bulk copy via the COPY ENGINE (cudaMemcpyAsync D2D,
// graph-capturable), then a tiny SM kernel rewrites only the W=129 window
// rows per batch (32*129 rows * 512B ~= 2.1 MB, 0.2% of tensor).
// Tests whether the DMA engines beat the SM-LSU sustained-copy cap
// (6.65-6.80 TB/s measured across all SM variants).
//
// Window kernel: one warp per (batch, window-row): 32 lanes x float4 = row.
// grid = B * W = 4128 warps = 516 blocks of 256 threads (8 warps).

__global__ __launch_bounds__(256) void window_update_kernel(
    const float4* __restrict__ ring4,     // B*M*D/4
    const float4* __restrict__ wvec4,     // B*D/4
    const float*  __restrict__ weights,   // B*W
    const float*  __restrict__ erase,     // B
    const float*  __restrict__ wgate,     // B
    const int*    __restrict__ idx,       // B*W
    float4*       __restrict__ out4)
{
    const int D4 = RB_D / 4;  // 32

    int warp = (blockIdx.x * blockDim.x + threadIdx.x) >> 5;   // 0 .. B*W-1
    int lane = threadIdx.x & 31;
    if (warp >= RB_B * RB_W) return;

    int b   = warp / RB_W;
    int off = warp - b * RB_W;          // 0..W-1

    int m = __ldg(&idx[b * RB_W + off]);   // exact target row (handles wrap)

    float w  = __ldg(&weights[b * RB_W + off]);
    float e  = __ldg(&erase[b]);
    float gt = __ldg(&wgate[b]);
    float keep = 1.0f - e * w;
    float add  = gt * w;

    long long base = ((long long)b * RB_M + m) * D4 + lane;
    float4 cur = __ldg(&ring4[base]);
    float4 wv  = __ldg(&wvec4[b * D4 + lane]);

    cur.x = cur.x * keep + add * wv.x;
    cur.y = cur.y * keep + add * wv.y;
    cur.z = cur.z * keep + add * wv.z;
    cur.w = cur.w * keep + add * wv.w;

    out4[base] = cur;
}

extern "C" void kernel_launch(void* const* d_in, const int* in_sizes, int n_in,
                              void* d_out, int out_size)
{
    const float4* ring4   = (const float4*)d_in[0];
    const float4* wvec4   = (const float4*)d_in[1];
    const float*  weights = (const float*)d_in[2];
    const float*  erase   = (const float*)d_in[3];
    const float*  wgate   = (const float*)d_in[4];
    const int*    idx     = (const int*)d_in[5];
    float4*       out4    = (float4*)d_out;

    const size_t bytes = (size_t)RB_B * RB_M * RB_D * sizeof(float);  // 512 MB

    // Bulk copy on the copy engine (async D2D — graph-capturable).
    cudaMemcpyAsync(out4, ring4, bytes, cudaMemcpyDeviceToDevice, 0);

    // Then overwrite the 129 window rows per batch (stream-ordered after copy).
    const int warps  = RB_B * RB_W;            // 4128
    const int threads = 256;                   // 8 warps per block
    const int blocks = (warps * 32 + threads - 1) / threads;   // 516

    window_update_kernel<<<blocks, threads>>>(ring4, wvec4, weights, erase,
                                              wgate, idx, out4);
}